// round 6
// baseline (speedup 1.0000x reference)
#include <cuda_runtime.h>
#include <cuda_bf16.h>
#include <cstdint>

// Problem constants (fixed by the reference)
#define NSIDE 64
#define NPIX  (12 * NSIDE * NSIDE)   // 49152
#define B     8
#define C     16
#define NN    524288                 // N

#define BINS    (B * NPIX)           // 393216
#define NBLK    1184                 // 148 SMs x 8 CTAs  (co-resident @ 256 thr)
#define NTHR    256
#define TOTTHR  (NBLK * NTHR)        // 303104

// Scratch: per-(batch,pixel) {sum, count}. One v2 REDG updates both.
// Zero at module load; phase 2 restores zeros (graph-replay safe).
__device__ float2 g_bin[BINS];

// Grid barrier state: monotonically increasing epoch counters (never reset —
// replay-safe; wraps only after ~3.6M launches, irrelevant).
__device__ unsigned g_arrive = 0;
__device__ volatile unsigned g_release = 0;

__device__ __forceinline__ void red_v2(float2* p, float v) {
    asm volatile("red.global.add.v2.f32 [%0], {%1, %2};"
                 :: "l"(p), "f"(v), "f"(1.0f) : "memory");
}

__global__ void __launch_bounds__(NTHR, 8)
fused_kernel(const float* __restrict__ vals,
             const int*   __restrict__ pix,
             float*       __restrict__ out) {
    const int tid = blockIdx.x * blockDim.x + threadIdx.x;

    // ---------------- Phase 1: scatter-accumulate ----------------
    // vec8 chunks: total B*NN/8 = 524288, grid-stride.
    const int per_batch = NN / 8;                // 65536 vec8 per batch
    for (int c = tid; c < B * per_batch; c += TOTTHR) {
        const int b = c / per_batch;
        const int v = c % per_batch;

        const float4* __restrict__ vp =
            reinterpret_cast<const float4*>(vals + (long long)b * C * NN);
        const int4* __restrict__ ip =
            reinterpret_cast<const int4*>(pix + (long long)b * NN);

        const float4 v0 = vp[2 * v + 0];
        const float4 v1 = vp[2 * v + 1];
        const int4   p0 = ip[2 * v + 0];
        const int4   p1 = ip[2 * v + 1];

        float2* __restrict__ bin = g_bin + b * NPIX;
        red_v2(bin + p0.x, v0.x);
        red_v2(bin + p0.y, v0.y);
        red_v2(bin + p0.z, v0.z);
        red_v2(bin + p0.w, v0.w);
        red_v2(bin + p1.x, v1.x);
        red_v2(bin + p1.y, v1.y);
        red_v2(bin + p1.z, v1.z);
        red_v2(bin + p1.w, v1.w);
    }

    // ---------------- Grid barrier (epoch-counting) ----------------
    __threadfence();          // make this thread's REDGs globally visible
    __syncthreads();          // whole block done + fenced
    if (threadIdx.x == 0) {
        unsigned t = atomicAdd(&g_arrive, 1u);
        unsigned epoch = t / NBLK;               // barrier instance
        if ((t % NBLK) == NBLK - 1) {
            // last arriver releases everyone
            atomicAdd((unsigned*)&g_release, 1u);    // g_release = epoch+1
        } else {
            while (g_release < epoch + 1u) {
                __nanosleep(64);
            }
        }
        __threadfence();      // acquire: bin data visible to this block
    }
    __syncthreads();

    // ---------------- Phase 2: mean + broadcast + reset ----------------
    // One thread per output float4 (4 threads share a bin), grid-stride.
    float4* __restrict__ o = reinterpret_cast<float4*>(out);
    for (int i = tid; i < BINS * 4; i += TOTTHR) {
        const int bin = i >> 2;
        float2 sc = g_bin[bin];                   // broadcast within 4-lane group
        if ((i & 3) == 0)
            g_bin[bin] = make_float2(0.f, 0.f);   // self-clean for next replay
        float m = __fdividef(sc.x, fmaxf(sc.y, 1.0f));
        o[i] = make_float4(m, m, m, m);
    }
}

// ---------------------------------------------------------------------------
extern "C" void kernel_launch(void* const* d_in, const int* in_sizes, int n_in,
                              void* d_out, int out_size) {
    const float* vals = (const float*)d_in[0];   // [B, C, N] f32
    const int*   pix  = (const int*)d_in[1];     // [B, N] i32
    float*       out  = (float*)d_out;           // [B, NPIX, C] f32

    (void)in_sizes; (void)n_in; (void)out_size;

    fused_kernel<<<NBLK, NTHR>>>(vals, pix, out);
}

// round 7
// speedup vs baseline: 1.0803x; 1.0803x over previous
#include <cuda_runtime.h>
#include <cuda_bf16.h>
#include <cstdint>

// Problem constants (fixed by the reference)
#define NSIDE 64
#define NPIX  (12 * NSIDE * NSIDE)   // 49152
#define B     8
#define C     16
#define NN    524288                 // N

#define BINS  (B * NPIX)             // 393216

// Scratch: per-(batch,pixel) packed f64 accumulator:
//   bin += (double)val + 2^32     (count in high bits, value sum in low bits)
// Decoded as c = rint(bin * 2^-32), s = bin - c*2^32.
// Max count/bin ~40 -> |bin| < 2^38; f64 has 52 mantissa bits -> value-sum
// precision ~4e-5 absolute, rel err ~1e-5 against the 1e-3 threshold.
// Zeroed at module load; write_kernel self-cleans for graph replay.
__device__ double g_bin[BINS];

#define CNT_SCALE 4294967296.0        // 2^32
#define CNT_INV   (1.0 / 4294967296.0)

__device__ __forceinline__ void red_f64(double* p, float v) {
    double d = (double)v + CNT_SCALE;
    asm volatile("red.global.add.f64 [%0], %1;" :: "l"(p), "d"(d) : "memory");
}

// ---------------------------------------------------------------------------
// Pass 1: scatter-accumulate. 8 elements per thread, front-batched vec4
// loads, ONE f64 REDG per element (sum+count packed) -> 2.1M atomic lanes.
// vals layout [B, C, N] -> channel 0 of batch b starts at b*C*N.
// ---------------------------------------------------------------------------
__global__ void accum_kernel(const float* __restrict__ vals,
                             const int*   __restrict__ pix) {
    const int t = blockIdx.x * blockDim.x + threadIdx.x;  // 0 .. B*N/8-1
    const int per_batch = NN / 8;                 // 65536 vec8 per batch
    const int b = t / per_batch;
    const int v = t % per_batch;

    const float4* __restrict__ vp =
        reinterpret_cast<const float4*>(vals + (long long)b * C * NN);
    const int4* __restrict__ ip =
        reinterpret_cast<const int4*>(pix + (long long)b * NN);

    const float4 v0 = vp[2 * v + 0];
    const float4 v1 = vp[2 * v + 1];
    const int4   p0 = ip[2 * v + 0];
    const int4   p1 = ip[2 * v + 1];

    double* __restrict__ bin = g_bin + b * NPIX;

    red_f64(bin + p0.x, v0.x);
    red_f64(bin + p0.y, v0.y);
    red_f64(bin + p0.z, v0.z);
    red_f64(bin + p0.w, v0.w);
    red_f64(bin + p1.x, v1.x);
    red_f64(bin + p1.y, v1.y);
    red_f64(bin + p1.z, v1.z);
    red_f64(bin + p1.w, v1.w);
}

// ---------------------------------------------------------------------------
// Pass 2: decode {count, sum}, mean, broadcast over C=16, reset bins.
// Grid-stride, 4 float4-writes per thread, hoisted bin loads (MLP=4).
// Output layout [B, NPIX, C]: bin i owns out float4s [4i .. 4i+3].
// ---------------------------------------------------------------------------
#define W_THREADS (BINS)            // 393216 threads, 4 iterations each
#define W_ITERS   4

__global__ void write_kernel(float* __restrict__ out) {
    const int tid = blockIdx.x * blockDim.x + threadIdx.x;   // 0 .. W_THREADS-1
    const int S = W_THREADS;

    double d[W_ITERS];
#pragma unroll
    for (int k = 0; k < W_ITERS; k++) {
        d[k] = g_bin[(tid + k * S) >> 2];
    }

    if ((tid & 3) == 0) {
#pragma unroll
        for (int k = 0; k < W_ITERS; k++) {
            g_bin[(tid + k * S) >> 2] = 0.0;      // self-clean for replay
        }
    }

    float4* __restrict__ o = reinterpret_cast<float4*>(out);
#pragma unroll
    for (int k = 0; k < W_ITERS; k++) {
        double c = rint(d[k] * CNT_INV);          // exact count
        double s = d[k] - c * CNT_SCALE;          // value sum
        float m = __fdividef((float)s, fmaxf((float)c, 1.0f));
        o[tid + k * S] = make_float4(m, m, m, m);
    }
}

// ---------------------------------------------------------------------------
extern "C" void kernel_launch(void* const* d_in, const int* in_sizes, int n_in,
                              void* d_out, int out_size) {
    const float* vals = (const float*)d_in[0];   // [B, C, N] f32
    const int*   pix  = (const int*)d_in[1];     // [B, N] i32
    float*       out  = (float*)d_out;           // [B, NPIX, C] f32

    (void)in_sizes; (void)n_in; (void)out_size;

    {
        const int n = B * (NN / 8);              // 524288 threads
        accum_kernel<<<n / 256, 256>>>(vals, pix);
    }
    {
        write_kernel<<<W_THREADS / 256, 256>>>(out);
    }
}

// round 8
// speedup vs baseline: 1.4079x; 1.3033x over previous
#include <cuda_runtime.h>
#include <cuda_bf16.h>
#include <cstdint>

// Problem constants (fixed by the reference)
#define NSIDE 64
#define NPIX  (12 * NSIDE * NSIDE)   // 49152
#define B     8
#define C     16
#define NN    524288                 // N

#define BINS  (B * NPIX)             // 393216

// Scratch: per-(batch,pixel) packed u64 integer accumulator:
//   bin += (int64)(val * 2^32) + 2^44
// Low 44 bits (signed, two's complement): fixed-point value sum.
// High bits: count. |sum| < ~300 -> |sum*2^32| < 2^41 << 2^43 bias margin.
// Integer LTS atomic add = full rate (unlike the FP64 unit tried in R7).
// Zeroed at module load; write_kernel self-cleans for graph replay.
__device__ unsigned long long g_bin[BINS];

#define CNT_UNIT  (1ULL << 44)
#define CNT_BIAS  (1ULL << 43)
#define FX_SCALE  4294967296.0f       // 2^32
#define FX_INV    (1.0f / 4294967296.0f)

__device__ __forceinline__ void red_u64(unsigned long long* p, float v) {
    unsigned long long d =
        (unsigned long long)((long long)(v * FX_SCALE)) + CNT_UNIT;
    asm volatile("red.global.add.u64 [%0], %1;" :: "l"(p), "l"(d) : "memory");
}

// ---------------------------------------------------------------------------
// Pass 1: scatter-accumulate. 8 elements per thread, front-batched vec4
// loads, ONE u64 integer REDG per element (sum+count packed) -> 2.1M lanes.
// vals layout [B, C, N] -> channel 0 of batch b starts at b*C*N.
// ---------------------------------------------------------------------------
__global__ void accum_kernel(const float* __restrict__ vals,
                             const int*   __restrict__ pix) {
    const int t = blockIdx.x * blockDim.x + threadIdx.x;  // 0 .. B*N/8-1
    const int per_batch = NN / 8;                 // 65536 vec8 per batch
    const int b = t / per_batch;
    const int v = t % per_batch;

    const float4* __restrict__ vp =
        reinterpret_cast<const float4*>(vals + (long long)b * C * NN);
    const int4* __restrict__ ip =
        reinterpret_cast<const int4*>(pix + (long long)b * NN);

    const float4 v0 = vp[2 * v + 0];
    const float4 v1 = vp[2 * v + 1];
    const int4   p0 = ip[2 * v + 0];
    const int4   p1 = ip[2 * v + 1];

    unsigned long long* __restrict__ bin = g_bin + b * NPIX;

    red_u64(bin + p0.x, v0.x);
    red_u64(bin + p0.y, v0.y);
    red_u64(bin + p0.z, v0.z);
    red_u64(bin + p0.w, v0.w);
    red_u64(bin + p1.x, v1.x);
    red_u64(bin + p1.y, v1.y);
    red_u64(bin + p1.z, v1.z);
    red_u64(bin + p1.w, v1.w);
}

// ---------------------------------------------------------------------------
// Pass 2: decode {count, sum}, mean, broadcast over C=16, reset bins.
// Grid-stride, 4 float4-writes per thread, hoisted bin loads (MLP=4).
// Output layout [B, NPIX, C]: bin i owns out float4s [4i .. 4i+3].
// ---------------------------------------------------------------------------
#define W_THREADS (BINS)            // 393216 threads, 4 iterations each
#define W_ITERS   4

__global__ void write_kernel(float* __restrict__ out) {
    const int tid = blockIdx.x * blockDim.x + threadIdx.x;   // 0 .. W_THREADS-1
    const int S = W_THREADS;

    unsigned long long d[W_ITERS];
#pragma unroll
    for (int k = 0; k < W_ITERS; k++) {
        d[k] = g_bin[(tid + k * S) >> 2];
    }

    if ((tid & 3) == 0) {
#pragma unroll
        for (int k = 0; k < W_ITERS; k++) {
            g_bin[(tid + k * S) >> 2] = 0ULL;     // self-clean for replay
        }
    }

    float4* __restrict__ o = reinterpret_cast<float4*>(out);
#pragma unroll
    for (int k = 0; k < W_ITERS; k++) {
        long long c = (long long)((d[k] + CNT_BIAS) >> 44);      // exact count
        long long s = (long long)d[k] - (c << 44);               // fixed-pt sum
        float sum = (float)s * FX_INV;
        float m = __fdividef(sum, fmaxf((float)c, 1.0f));
        o[tid + k * S] = make_float4(m, m, m, m);
    }
}

// ---------------------------------------------------------------------------
extern "C" void kernel_launch(void* const* d_in, const int* in_sizes, int n_in,
                              void* d_out, int out_size) {
    const float* vals = (const float*)d_in[0];   // [B, C, N] f32
    const int*   pix  = (const int*)d_in[1];     // [B, N] i32
    float*       out  = (float*)d_out;           // [B, NPIX, C] f32

    (void)in_sizes; (void)n_in; (void)out_size;

    {
        const int n = B * (NN / 8);              // 524288 threads
        accum_kernel<<<n / 256, 256>>>(vals, pix);
    }
    {
        write_kernel<<<W_THREADS / 256, 256>>>(out);
    }
}